// round 13
// baseline (speedup 1.0000x reference)
#include <cuda_runtime.h>
#include <cuda_bf16.h>
#include <cuda_fp16.h>
#include <math.h>
#include <stdint.h>

#define BATCH 2
#define SEQ   4096
#define DMODEL 512
#define NHEAD 8
#define HDIM  64
#define MROWS (BATCH*SEQ)
#define MAXREL 2

typedef unsigned long long ull;

// scratch
__device__ float g_A[MROWS * DMODEL];
__device__ unsigned short g_Qh[MROWS * DMODEL];   // fp16
__device__ unsigned short g_Kh[MROWS * DMODEL];   // fp16
__device__ unsigned short g_Vh[MROWS * DMODEL];   // fp16

// split (a,b) into bf16 hi-pair + lo-pair words (GEMM internals): h={lo=a,hi=b}
__device__ __forceinline__ void split2(float a, float b, uint32_t& h, uint32_t& l) {
    asm("cvt.rn.bf16x2.f32 %0, %1, %2;" : "=r"(h) : "f"(b), "f"(a));
    float ha = __uint_as_float(h << 16);
    float hb = __uint_as_float(h & 0xffff0000u);
    float ra = a - ha, rb = b - hb;
    asm("cvt.rn.bf16x2.f32 %0, %1, %2;" : "=r"(l) : "f"(rb), "f"(ra));
}
// pack (a,b) -> fp16x2 {lo=a, hi=b}
__device__ __forceinline__ uint32_t pkhf2(float a, float b) {
    uint32_t h;
    asm("cvt.rn.f16x2.f32 %0, %1, %2;" : "=r"(h) : "f"(b), "f"(a));
    return h;
}

static __device__ __forceinline__ uint32_t smem_u32(const void* p) {
    uint32_t a;
    asm("{ .reg .u64 t; cvta.to.shared.u64 t, %1; cvt.u32.u64 %0, t; }" : "=r"(a) : "l"(p));
    return a;
}
__device__ __forceinline__ void ldsm4(uint32_t* r, uint32_t addr) {
    asm volatile("ldmatrix.sync.aligned.m8n8.x4.shared.b16 {%0,%1,%2,%3}, [%4];"
                 : "=r"(r[0]), "=r"(r[1]), "=r"(r[2]), "=r"(r[3]) : "r"(addr));
}
__device__ __forceinline__ void ldsm4t(uint32_t* r, uint32_t addr) {
    asm volatile("ldmatrix.sync.aligned.m8n8.x4.trans.shared.b16 {%0,%1,%2,%3}, [%4];"
                 : "=r"(r[0]), "=r"(r[1]), "=r"(r[2]), "=r"(r[3]) : "r"(addr));
}
// bf16 mma (GEMM)
__device__ __forceinline__ void mmabf16(float* c, const uint32_t* a, uint32_t b0, uint32_t b1) {
    asm volatile("mma.sync.aligned.m16n8k16.row.col.f32.bf16.bf16.f32 "
                 "{%0,%1,%2,%3}, {%4,%5,%6,%7}, {%8,%9}, {%0,%1,%2,%3};"
                 : "+f"(c[0]), "+f"(c[1]), "+f"(c[2]), "+f"(c[3])
                 : "r"(a[0]), "r"(a[1]), "r"(a[2]), "r"(a[3]), "r"(b0), "r"(b1));
}
// fp16 mma (attention)
__device__ __forceinline__ void mmaf16(float* c, const uint32_t* a, uint32_t b0, uint32_t b1) {
    asm volatile("mma.sync.aligned.m16n8k16.row.col.f32.f16.f16.f32 "
                 "{%0,%1,%2,%3}, {%4,%5,%6,%7}, {%8,%9}, {%0,%1,%2,%3};"
                 : "+f"(c[0]), "+f"(c[1]), "+f"(c[2]), "+f"(c[3])
                 : "r"(a[0]), "r"(a[1]), "r"(a[2]), "r"(a[3]), "r"(b0), "r"(b1));
}
__device__ __forceinline__ void cpa16(uint32_t d, const void* s) {
    asm volatile("cp.async.cg.shared.global [%0], [%1], 16;" :: "r"(d), "l"(s));
}
#define CP_COMMIT() asm volatile("cp.async.commit_group;" ::: "memory")
#define CP_WAIT1()  asm volatile("cp.async.wait_group 1;" ::: "memory")

#define SW128(o) ((o) ^ (((o) >> 3) & 0x70))
#define SW64(o)  ((o) ^ (((o) >> 3) & 0x30))

// ---------------------------------------------------------------------------
// Tensor-core GEMM, 3-term bf16 split internals, DOUBLE-BUFFERED smem:
// one __syncthreads per BK=32 chunk. Dynamic smem 64KB (2 x 32KB buffers).
// mode 0: fp32 out.  mode 1: fp16 out, value = scale*(acc+bias).
// ---------------------------------------------------------------------------
#define GEMM_SMEM 65536
#define GBUF 32768
#define GXH 0
#define GXL 8192
#define GWH 16384
#define GWL 24576

__global__ __launch_bounds__(256, 2) void gemm_bf16(const float* __restrict__ X,
                                                    const float* __restrict__ W,
                                                    const float* __restrict__ bias,
                                                    float* __restrict__ Cf,
                                                    unsigned short* __restrict__ Ch,
                                                    float scale, int mode)
{
    extern __shared__ char gsm[];
    const uint32_t sb = smem_u32(gsm);

    const int tid = threadIdx.x;
    const int w = tid >> 5;
    const int lane = tid & 31;
    const int m0 = blockIdx.y * 128, n0 = blockIdx.x * 128;

    const int row = tid >> 1;
    const int half = tid & 1;

    const float* Xg = X + (size_t)(m0 + row) * DMODEL + half * 16;
    const float* Wg = W + (size_t)(n0 + row) * DMODEL + half * 16;

    const uint32_t base_a = (uint32_t)((16 * w + (lane & 15)) * 64 + (lane >> 4) * 16);
    const uint32_t base_b = (uint32_t)(((lane & 7) + ((lane & 16) >> 1)) * 64 + ((lane >> 3) & 1) * 16);
    const uint32_t soff = SW64((uint32_t)(row * 64 + half * 32));

    float cs[16][4];
#pragma unroll
    for (int i = 0; i < 16; i++)
#pragma unroll
        for (int j = 0; j < 4; j++) cs[i][j] = 0.f;

    float4 xr[4], wr[4];
#pragma unroll
    for (int i = 0; i < 4; i++) {
        xr[i] = *(const float4*)(Xg + i * 4);
        wr[i] = *(const float4*)(Wg + i * 4);
    }

    // initial STS into buffer 0
    {
        char* bp = gsm;
#pragma unroll
        for (int i = 0; i < 4; i++) {
            uint32_t h0, l0, h1, l1;
            split2(xr[i].x, xr[i].y, h0, l0);
            split2(xr[i].z, xr[i].w, h1, l1);
            const uint32_t off = SW64((uint32_t)(row * 64 + half * 32 + i * 8));
            *(uint2*)(bp + GXH + off) = make_uint2(h0, h1);
            *(uint2*)(bp + GXL + off) = make_uint2(l0, l1);
            split2(wr[i].x, wr[i].y, h0, l0);
            split2(wr[i].z, wr[i].w, h1, l1);
            *(uint2*)(bp + GWH + off) = make_uint2(h0, h1);
            *(uint2*)(bp + GWL + off) = make_uint2(l0, l1);
        }
    }

    for (int ks = 0; ks < DMODEL / 32; ks++) {
        __syncthreads();   // STS(ks) visible; all warps done computing buf (ks&1) from 2 iters ago

        // prefetch next chunk's fp32 (issued early, consumed after compute)
        if (ks + 1 < DMODEL / 32) {
            const int k1 = (ks + 1) * 32;
#pragma unroll
            for (int i = 0; i < 4; i++) {
                xr[i] = *(const float4*)(Xg + k1 + i * 4);
                wr[i] = *(const float4*)(Wg + k1 + i * 4);
            }
        }

        // compute from buffer ks&1
        const uint32_t bp = sb + (uint32_t)(ks & 1) * GBUF;
#pragma unroll
        for (int c = 0; c < 2; c++) {
            uint32_t ah[4], al[4];
            const uint32_t aoff = SW64(base_a + 32u * c);
            ldsm4(ah, bp + GXH + aoff);
            ldsm4(al, bp + GXL + aoff);
#pragma unroll
            for (int j2 = 0; j2 < 8; j2++) {
                uint32_t bh[4], bl[4];
                const uint32_t boff = SW64(base_b + 1024u * j2 + 32u * c);
                ldsm4(bh, bp + GWH + boff);
                ldsm4(bl, bp + GWL + boff);
                mmabf16(cs[2 * j2], ah, bh[0], bh[1]);
                mmabf16(cs[2 * j2], ah, bl[0], bl[1]);
                mmabf16(cs[2 * j2], al, bh[0], bh[1]);
                mmabf16(cs[2 * j2 + 1], ah, bh[2], bh[3]);
                mmabf16(cs[2 * j2 + 1], ah, bl[2], bl[3]);
                mmabf16(cs[2 * j2 + 1], al, bh[2], bh[3]);
            }
        }

        // split + STS next chunk into the other buffer
        if (ks + 1 < DMODEL / 32) {
            char* np = gsm + ((ks + 1) & 1) * GBUF;
#pragma unroll
            for (int i = 0; i < 4; i++) {
                uint32_t h0, l0, h1, l1;
                split2(xr[i].x, xr[i].y, h0, l0);
                split2(xr[i].z, xr[i].w, h1, l1);
                const uint32_t off = soff + (uint32_t)(i * 8);
                // note: SW64 swizzle of (row*64 + half*32 + i*8) == soff + i*8
                // only when i*8 doesn't cross the swizzle bits; recompute safely:
                const uint32_t offs = SW64((uint32_t)(row * 64 + half * 32 + i * 8));
                *(uint2*)(np + GXH + offs) = make_uint2(h0, h1);
                *(uint2*)(np + GXL + offs) = make_uint2(l0, l1);
                split2(wr[i].x, wr[i].y, h0, l0);
                split2(wr[i].z, wr[i].w, h1, l1);
                *(uint2*)(np + GWH + offs) = make_uint2(h0, h1);
                *(uint2*)(np + GWL + offs) = make_uint2(l0, l1);
                (void)off;
            }
        }
    }

    const int rr = m0 + 16 * w + (lane >> 2);
    const int cc = 2 * (lane & 3);
    if (mode == 0) {
#pragma unroll
        for (int t = 0; t < 16; t++) {
            const int col = n0 + 8 * t + cc;
            const float2 bv = *(const float2*)(bias + col);
            float* C0 = Cf + (size_t)rr * DMODEL + col;
            *(float2*)C0 = make_float2(cs[t][0] + bv.x, cs[t][1] + bv.y);
            *(float2*)(C0 + 8 * DMODEL) = make_float2(cs[t][2] + bv.x, cs[t][3] + bv.y);
        }
    } else {
#pragma unroll
        for (int t = 0; t < 16; t++) {
            const int col = n0 + 8 * t + cc;
            const float2 bv = *(const float2*)(bias + col);
            *(uint32_t*)(Ch + (size_t)rr * DMODEL + col) =
                pkhf2(scale * (cs[t][0] + bv.x), scale * (cs[t][1] + bv.y));
            *(uint32_t*)(Ch + (size_t)(rr + 8) * DMODEL + col) =
                pkhf2(scale * (cs[t][2] + bv.x), scale * (cs[t][3] + bv.y));
        }
    }
}

// ===========================================================================
// mma.sync attention — fp16 single-term (R11 inner code), 128-key stages
// (2 x 64-key subtiles), 3-stage cp.async. No Q hoisting, no fragment arrays
// (register-neutral vs R11).
// ===========================================================================

#define OQH 0
#define OST 16384
#define STAGE_SZ 32768          /* K 16KB + V 16KB (128 keys) */
#define SKH 0
#define SVH 16384
#define NSTAGE 3
#define ATTN_SMEM (OST + NSTAGE * STAGE_SZ)   /* 112 KB */
#define NSTG (SEQ / 128)        /* 32 */

__global__ __launch_bounds__(256, 2) void attn_kernel(
    const unsigned short* __restrict__ Qh,
    const unsigned short* __restrict__ Kh,
    const unsigned short* __restrict__ Vh,
    const float* __restrict__ relpos, float* __restrict__ Out)
{
    extern __shared__ char smp[];
    const uint32_t sb = smem_u32(smp);

    const int tid = threadIdx.x;
    const int w = tid >> 5;
    const int lane = tid & 31;
    const int b = blockIdx.z, h = blockIdx.y;
    const int q0 = blockIdx.x * 128;

    const float rb0 = relpos[h * 5 + 0];
    const float rb1 = relpos[h * 5 + 1];
    const float rb2 = relpos[h * 5 + 2];
    const float rb3 = relpos[h * 5 + 3];
    const float rb4 = relpos[h * 5 + 4];

    // ---- Q tile load (128 rows x 128B, SW128) ----
    {
        const int row = tid >> 1;
        const int ch0 = (tid & 1) * 4;
        const size_t gb = (size_t)(b * SEQ + q0 + row) * DMODEL + h * HDIM + ch0 * 8;
#pragma unroll
        for (int ci = 0; ci < 4; ci++) {
            const uint32_t off = SW128((uint32_t)(row * 128 + (ch0 + ci) * 16));
            *(uint4*)(smp + OQH + off) = *(const uint4*)(Qh + gb + ci * 8);
        }
    }

    // ---- K/V stage loader: 128 rows x 128B each; 4 chunks/thread/array ----
    const int krow = tid >> 1;
    const int kch0 = (tid & 1) * 4;
    const size_t kgb0 = (size_t)(b * SEQ + krow) * DMODEL + h * HDIM + kch0 * 8;

    // prologue: stages 0,1
#pragma unroll
    for (int s = 0; s < NSTAGE - 1; s++) {
        const uint32_t st = sb + OST + s * STAGE_SZ;
        const size_t gb = kgb0 + (size_t)(s * 128) * DMODEL;
#pragma unroll
        for (int ci = 0; ci < 4; ci++) {
            const uint32_t off = SW128((uint32_t)(krow * 128 + (kch0 + ci) * 16));
            cpa16(st + SKH + off, Kh + gb + ci * 8);
            cpa16(st + SVH + off, Vh + gb + ci * 8);
        }
        CP_COMMIT();
    }

    const uint32_t base_qa = (uint32_t)((16 * w + (lane & 15)) * 128 + 16 * (lane >> 4));
    const uint32_t base_kb = (uint32_t)(((lane & 7) + ((lane & 16) >> 1)) * 128 + ((lane >> 3) & 1) * 16);
    const uint32_t base_vb = (uint32_t)(((lane & 7) + (lane & 8)) * 128 + ((lane >> 4) & 1) * 16);

    float co[8][4];
#pragma unroll
    for (int i = 0; i < 8; i++)
#pragma unroll
        for (int j = 0; j < 4; j++) co[i][j] = 0.f;
    float sum0 = 0.f, sum1 = 0.f;

    const int r0g = q0 + 16 * w + (lane >> 2);
    const int kcol_off = 2 * (lane & 3);

    for (int kt = 0; kt < NSTG; kt++) {
        CP_WAIT1();           // stage kt arrived
        __syncthreads();      // all threads done with buffer being overwritten; Q visible (kt=0)

        // issue stage kt+2 into buffer (kt+2)%3 (its contents were consumed in iter kt-1)
        if (kt + NSTAGE - 1 < NSTG) {
            const uint32_t st = sb + OST + ((kt + NSTAGE - 1) % NSTAGE) * STAGE_SZ;
            const size_t gb = kgb0 + (size_t)((kt + NSTAGE - 1) * 128) * DMODEL;
#pragma unroll
            for (int ci = 0; ci < 4; ci++) {
                const uint32_t off = SW128((uint32_t)(krow * 128 + (kch0 + ci) * 16));
                cpa16(st + SKH + off, Kh + gb + ci * 8);
                cpa16(st + SVH + off, Vh + gb + ci * 8);
            }
        }
        CP_COMMIT();

        const uint32_t stg = sb + OST + (kt % NSTAGE) * STAGE_SZ;

#pragma unroll
        for (int s2 = 0; s2 < 2; s2++) {
            const int k0 = kt * 128 + s2 * 64;
            const uint32_t KHb = stg + SKH + s2 * 8192;
            const uint32_t VHb = stg + SVH + s2 * 8192;
            const uint32_t QHb = sb + OQH;

            // ---- S = Q @ K^T (fp16, R11 structure) ----
            float cs[8][4];
#pragma unroll
            for (int i = 0; i < 8; i++)
#pragma unroll
                for (int j = 0; j < 4; j++) cs[i][j] = 0.f;

#pragma unroll
            for (int c = 0; c < 4; c++) {
                uint32_t ah[4];
                ldsm4(ah, QHb + SW128(base_qa + 32 * c));
#pragma unroll
                for (int j2 = 0; j2 < 4; j2++) {
                    uint32_t bh[4];
                    ldsm4(bh, KHb + SW128(base_kb + 2048u * j2 + 32u * c));
                    mmaf16(cs[2 * j2], ah, bh[0], bh[1]);
                    mmaf16(cs[2 * j2 + 1], ah, bh[2], bh[3]);
                }
            }

            // ---- bias + exp + rowsum ----
            const bool uni = (k0 - (q0 + 127) > MAXREL) || ((k0 + 63) - q0 < -MAXREL);
            if (uni) {
                const float ub = (k0 > q0) ? rb4 : rb0;
#pragma unroll
                for (int j = 0; j < 8; j++) {
                    cs[j][0] = __expf(cs[j][0] + ub);
                    cs[j][1] = __expf(cs[j][1] + ub);
                    cs[j][2] = __expf(cs[j][2] + ub);
                    cs[j][3] = __expf(cs[j][3] + ub);
                }
            } else {
#pragma unroll
                for (int j = 0; j < 8; j++) {
                    const int kc = k0 + 8 * j + kcol_off;
#pragma unroll
                    for (int i = 0; i < 4; i++) {
                        const int rel = (kc + (i & 1)) - (r0g + (i >> 1) * 8);
                        const float bb = rel <= -MAXREL ? rb0 :
                                         rel >= MAXREL ? rb4 :
                                         rel == -1 ? rb1 : (rel == 0 ? rb2 : rb3);
                        cs[j][i] = __expf(cs[j][i] + bb);
                    }
                }
            }
#pragma unroll
            for (int j = 0; j < 8; j++) {
                sum0 += cs[j][0] + cs[j][1];
                sum1 += cs[j][2] + cs[j][3];
            }

            // ---- O += P @ V (fp16, R11 structure) ----
#pragma unroll
            for (int kc = 0; kc < 4; kc++) {
                uint32_t ph[4];
                ph[0] = pkhf2(cs[2 * kc][0],     cs[2 * kc][1]);
                ph[1] = pkhf2(cs[2 * kc][2],     cs[2 * kc][3]);
                ph[2] = pkhf2(cs[2 * kc + 1][0], cs[2 * kc + 1][1]);
                ph[3] = pkhf2(cs[2 * kc + 1][2], cs[2 * kc + 1][3]);
#pragma unroll
                for (int jv = 0; jv < 4; jv++) {
                    uint32_t vh[4];
                    ldsm4t(vh, VHb + SW128(base_vb + 2048u * kc + 32u * jv));
                    mmaf16(co[2 * jv], ph, vh[0], vh[1]);
                    mmaf16(co[2 * jv + 1], ph, vh[2], vh[3]);
                }
            }
        }
    }

    sum0 += __shfl_xor_sync(0xFFFFFFFFu, sum0, 1);
    sum0 += __shfl_xor_sync(0xFFFFFFFFu, sum0, 2);
    sum1 += __shfl_xor_sync(0xFFFFFFFFu, sum1, 1);
    sum1 += __shfl_xor_sync(0xFFFFFFFFu, sum1, 2);
    const float inv0 = 1.0f / sum0;
    const float inv1 = 1.0f / sum1;

    {
        float* O0 = Out + (size_t)(b * SEQ + r0g) * DMODEL + h * HDIM + kcol_off;
        float* O1 = O0 + 8 * DMODEL;
#pragma unroll
        for (int j = 0; j < 8; j++) {
            *(float2*)(O0 + 8 * j) = make_float2(co[j][0] * inv0, co[j][1] * inv0);
            *(float2*)(O1 + 8 * j) = make_float2(co[j][2] * inv1, co[j][3] * inv1);
        }
    }
}

// ---------------------------------------------------------------------------
extern "C" void kernel_launch(void* const* d_in, const int* in_sizes, int n_in,
                              void* d_out, int out_size)
{
    const float* q  = (const float*)d_in[0];
    const float* k  = (const float*)d_in[1];
    const float* v  = (const float*)d_in[2];
    const float* Wq = (const float*)d_in[3];
    const float* bq = (const float*)d_in[4];
    const float* Wk = (const float*)d_in[5];
    const float* bk = (const float*)d_in[6];
    const float* Wv = (const float*)d_in[7];
    const float* bv = (const float*)d_in[8];
    const float* Wo = (const float*)d_in[9];
    const float* bo = (const float*)d_in[10];
    const float* rp = (const float*)d_in[11];
    float* out = (float*)d_out;

    float *dA;
    unsigned short *dQh, *dKh, *dVh;
    cudaGetSymbolAddress((void**)&dA, g_A);
    cudaGetSymbolAddress((void**)&dQh, g_Qh);
    cudaGetSymbolAddress((void**)&dKh, g_Kh);
    cudaGetSymbolAddress((void**)&dVh, g_Vh);

    cudaFuncSetAttribute(attn_kernel, cudaFuncAttributeMaxDynamicSharedMemorySize,
                         ATTN_SMEM);
    cudaFuncSetAttribute(gemm_bf16, cudaFuncAttributeMaxDynamicSharedMemorySize,
                         GEMM_SMEM);

    dim3 gblk(256);
    dim3 ggrid(DMODEL / 128, MROWS / 128);   // (4, 64)

    gemm_bf16<<<ggrid, gblk, GEMM_SMEM>>>(q, Wq, bq, nullptr, dQh, 0.125f, 1);
    gemm_bf16<<<ggrid, gblk, GEMM_SMEM>>>(k, Wk, bk, nullptr, dKh, 1.0f, 1);
    gemm_bf16<<<ggrid, gblk, GEMM_SMEM>>>(v, Wv, bv, nullptr, dVh, 1.0f, 1);

    dim3 agrid(SEQ / 128, NHEAD, BATCH);     // (32, 8, 2)
    attn_kernel<<<agrid, gblk, ATTN_SMEM>>>(dQh, dKh, dVh, rp, dA);

    gemm_bf16<<<ggrid, gblk, GEMM_SMEM>>>(dA, Wo, bo, out, nullptr, 1.0f, 0);
}

// round 14
// speedup vs baseline: 1.1120x; 1.1120x over previous
#include <cuda_runtime.h>
#include <cuda_bf16.h>
#include <cuda_fp16.h>
#include <math.h>
#include <stdint.h>

#define BATCH 2
#define SEQ   4096
#define DMODEL 512
#define NHEAD 8
#define HDIM  64
#define MROWS (BATCH*SEQ)
#define MAXREL 2

typedef unsigned long long ull;

// scratch
__device__ float g_A[MROWS * DMODEL];
__device__ unsigned short g_Qh[MROWS * DMODEL];   // fp16
__device__ unsigned short g_Kh[MROWS * DMODEL];   // fp16
__device__ unsigned short g_Vh[MROWS * DMODEL];   // fp16

// split (a,b) into bf16 hi-pair + lo-pair words (GEMM internals): h={lo=a,hi=b}
__device__ __forceinline__ void split2(float a, float b, uint32_t& h, uint32_t& l) {
    asm("cvt.rn.bf16x2.f32 %0, %1, %2;" : "=r"(h) : "f"(b), "f"(a));
    float ha = __uint_as_float(h << 16);
    float hb = __uint_as_float(h & 0xffff0000u);
    float ra = a - ha, rb = b - hb;
    asm("cvt.rn.bf16x2.f32 %0, %1, %2;" : "=r"(l) : "f"(rb), "f"(ra));
}
// pack (a,b) -> fp16x2 {lo=a, hi=b}
__device__ __forceinline__ uint32_t pkhf2(float a, float b) {
    uint32_t h;
    asm("cvt.rn.f16x2.f32 %0, %1, %2;" : "=r"(h) : "f"(b), "f"(a));
    return h;
}

static __device__ __forceinline__ uint32_t smem_u32(const void* p) {
    uint32_t a;
    asm("{ .reg .u64 t; cvta.to.shared.u64 t, %1; cvt.u32.u64 %0, t; }" : "=r"(a) : "l"(p));
    return a;
}
__device__ __forceinline__ void ldsm4(uint32_t* r, uint32_t addr) {
    asm volatile("ldmatrix.sync.aligned.m8n8.x4.shared.b16 {%0,%1,%2,%3}, [%4];"
                 : "=r"(r[0]), "=r"(r[1]), "=r"(r[2]), "=r"(r[3]) : "r"(addr));
}
__device__ __forceinline__ void ldsm4t(uint32_t* r, uint32_t addr) {
    asm volatile("ldmatrix.sync.aligned.m8n8.x4.trans.shared.b16 {%0,%1,%2,%3}, [%4];"
                 : "=r"(r[0]), "=r"(r[1]), "=r"(r[2]), "=r"(r[3]) : "r"(addr));
}
// bf16 mma (GEMM)
__device__ __forceinline__ void mmabf16(float* c, const uint32_t* a, uint32_t b0, uint32_t b1) {
    asm volatile("mma.sync.aligned.m16n8k16.row.col.f32.bf16.bf16.f32 "
                 "{%0,%1,%2,%3}, {%4,%5,%6,%7}, {%8,%9}, {%0,%1,%2,%3};"
                 : "+f"(c[0]), "+f"(c[1]), "+f"(c[2]), "+f"(c[3])
                 : "r"(a[0]), "r"(a[1]), "r"(a[2]), "r"(a[3]), "r"(b0), "r"(b1));
}
// fp16 mma (attention)
__device__ __forceinline__ void mmaf16(float* c, const uint32_t* a, uint32_t b0, uint32_t b1) {
    asm volatile("mma.sync.aligned.m16n8k16.row.col.f32.f16.f16.f32 "
                 "{%0,%1,%2,%3}, {%4,%5,%6,%7}, {%8,%9}, {%0,%1,%2,%3};"
                 : "+f"(c[0]), "+f"(c[1]), "+f"(c[2]), "+f"(c[3])
                 : "r"(a[0]), "r"(a[1]), "r"(a[2]), "r"(a[3]), "r"(b0), "r"(b1));
}
__device__ __forceinline__ void cpa16(uint32_t d, const void* s) {
    asm volatile("cp.async.cg.shared.global [%0], [%1], 16;" :: "r"(d), "l"(s));
}
#define CP_COMMIT() asm volatile("cp.async.commit_group;" ::: "memory")
#define CP_WAIT2()  asm volatile("cp.async.wait_group 2;" ::: "memory")

#define SW128(o) ((o) ^ (((o) >> 3) & 0x70))
#define SW64(o)  ((o) ^ (((o) >> 3) & 0x30))

// ---------------------------------------------------------------------------
// Tensor-core GEMM, 3-term bf16 split internals, DOUBLE-BUFFERED smem (R13):
// one __syncthreads per BK=32 chunk. Dynamic smem 64KB (2 x 32KB buffers).
// mode 0: fp32 out.  mode 1: fp16 out, value = scale*(acc+bias).
// ---------------------------------------------------------------------------
#define GEMM_SMEM 65536
#define GBUF 32768
#define GXH 0
#define GXL 8192
#define GWH 16384
#define GWL 24576

__global__ __launch_bounds__(256, 2) void gemm_bf16(const float* __restrict__ X,
                                                    const float* __restrict__ W,
                                                    const float* __restrict__ bias,
                                                    float* __restrict__ Cf,
                                                    unsigned short* __restrict__ Ch,
                                                    float scale, int mode)
{
    extern __shared__ char gsm[];
    const uint32_t sb = smem_u32(gsm);

    const int tid = threadIdx.x;
    const int w = tid >> 5;
    const int lane = tid & 31;
    const int m0 = blockIdx.y * 128, n0 = blockIdx.x * 128;

    const int row = tid >> 1;
    const int half = tid & 1;

    const float* Xg = X + (size_t)(m0 + row) * DMODEL + half * 16;
    const float* Wg = W + (size_t)(n0 + row) * DMODEL + half * 16;

    const uint32_t base_a = (uint32_t)((16 * w + (lane & 15)) * 64 + (lane >> 4) * 16);
    const uint32_t base_b = (uint32_t)(((lane & 7) + ((lane & 16) >> 1)) * 64 + ((lane >> 3) & 1) * 16);

    float cs[16][4];
#pragma unroll
    for (int i = 0; i < 16; i++)
#pragma unroll
        for (int j = 0; j < 4; j++) cs[i][j] = 0.f;

    float4 xr[4], wr[4];
#pragma unroll
    for (int i = 0; i < 4; i++) {
        xr[i] = *(const float4*)(Xg + i * 4);
        wr[i] = *(const float4*)(Wg + i * 4);
    }

    // initial STS into buffer 0
    {
        char* bp = gsm;
#pragma unroll
        for (int i = 0; i < 4; i++) {
            uint32_t h0, l0, h1, l1;
            split2(xr[i].x, xr[i].y, h0, l0);
            split2(xr[i].z, xr[i].w, h1, l1);
            const uint32_t off = SW64((uint32_t)(row * 64 + half * 32 + i * 8));
            *(uint2*)(bp + GXH + off) = make_uint2(h0, h1);
            *(uint2*)(bp + GXL + off) = make_uint2(l0, l1);
            split2(wr[i].x, wr[i].y, h0, l0);
            split2(wr[i].z, wr[i].w, h1, l1);
            *(uint2*)(bp + GWH + off) = make_uint2(h0, h1);
            *(uint2*)(bp + GWL + off) = make_uint2(l0, l1);
        }
    }

    for (int ks = 0; ks < DMODEL / 32; ks++) {
        __syncthreads();   // STS(ks) visible; all warps done with buf (ks&1) from 2 iters ago

        if (ks + 1 < DMODEL / 32) {
            const int k1 = (ks + 1) * 32;
#pragma unroll
            for (int i = 0; i < 4; i++) {
                xr[i] = *(const float4*)(Xg + k1 + i * 4);
                wr[i] = *(const float4*)(Wg + k1 + i * 4);
            }
        }

        const uint32_t bp = sb + (uint32_t)(ks & 1) * GBUF;
#pragma unroll
        for (int c = 0; c < 2; c++) {
            uint32_t ah[4], al[4];
            const uint32_t aoff = SW64(base_a + 32u * c);
            ldsm4(ah, bp + GXH + aoff);
            ldsm4(al, bp + GXL + aoff);
#pragma unroll
            for (int j2 = 0; j2 < 8; j2++) {
                uint32_t bh[4], bl[4];
                const uint32_t boff = SW64(base_b + 1024u * j2 + 32u * c);
                ldsm4(bh, bp + GWH + boff);
                ldsm4(bl, bp + GWL + boff);
                mmabf16(cs[2 * j2], ah, bh[0], bh[1]);
                mmabf16(cs[2 * j2], ah, bl[0], bl[1]);
                mmabf16(cs[2 * j2], al, bh[0], bh[1]);
                mmabf16(cs[2 * j2 + 1], ah, bh[2], bh[3]);
                mmabf16(cs[2 * j2 + 1], ah, bl[2], bl[3]);
                mmabf16(cs[2 * j2 + 1], al, bh[2], bh[3]);
            }
        }

        if (ks + 1 < DMODEL / 32) {
            char* np = gsm + ((ks + 1) & 1) * GBUF;
#pragma unroll
            for (int i = 0; i < 4; i++) {
                uint32_t h0, l0, h1, l1;
                split2(xr[i].x, xr[i].y, h0, l0);
                split2(xr[i].z, xr[i].w, h1, l1);
                const uint32_t offs = SW64((uint32_t)(row * 64 + half * 32 + i * 8));
                *(uint2*)(np + GXH + offs) = make_uint2(h0, h1);
                *(uint2*)(np + GXL + offs) = make_uint2(l0, l1);
                split2(wr[i].x, wr[i].y, h0, l0);
                split2(wr[i].z, wr[i].w, h1, l1);
                *(uint2*)(np + GWH + offs) = make_uint2(h0, h1);
                *(uint2*)(np + GWL + offs) = make_uint2(l0, l1);
            }
        }
    }

    const int rr = m0 + 16 * w + (lane >> 2);
    const int cc = 2 * (lane & 3);
    if (mode == 0) {
#pragma unroll
        for (int t = 0; t < 16; t++) {
            const int col = n0 + 8 * t + cc;
            const float2 bv = *(const float2*)(bias + col);
            float* C0 = Cf + (size_t)rr * DMODEL + col;
            *(float2*)C0 = make_float2(cs[t][0] + bv.x, cs[t][1] + bv.y);
            *(float2*)(C0 + 8 * DMODEL) = make_float2(cs[t][2] + bv.x, cs[t][3] + bv.y);
        }
    } else {
#pragma unroll
        for (int t = 0; t < 16; t++) {
            const int col = n0 + 8 * t + cc;
            const float2 bv = *(const float2*)(bias + col);
            *(uint32_t*)(Ch + (size_t)rr * DMODEL + col) =
                pkhf2(scale * (cs[t][0] + bv.x), scale * (cs[t][1] + bv.y));
            *(uint32_t*)(Ch + (size_t)(rr + 8) * DMODEL + col) =
                pkhf2(scale * (cs[t][2] + bv.x), scale * (cs[t][3] + bv.y));
        }
    }
}

// ===========================================================================
// mma.sync attention — R11 VERBATIM: fp16 single-term, KV tile 64,
// 4-stage cp.async, 80KB smem, 128 regs, 2 CTAs/SM.
// ===========================================================================

#define OQH 0
#define OST 16384
#define STAGE_SZ 16384
#define SKH 0
#define SVH 8192
#define NSTAGE 4
#define ATTN_SMEM (OST + NSTAGE * STAGE_SZ)   /* 80 KB */
#define NKT (SEQ / 64)

__global__ __launch_bounds__(256, 2) void attn_kernel(
    const unsigned short* __restrict__ Qh,
    const unsigned short* __restrict__ Kh,
    const unsigned short* __restrict__ Vh,
    const float* __restrict__ relpos, float* __restrict__ Out)
{
    extern __shared__ char smp[];
    const uint32_t sb = smem_u32(smp);

    const int tid = threadIdx.x;
    const int w = tid >> 5;
    const int lane = tid & 31;
    const int b = blockIdx.z, h = blockIdx.y;
    const int q0 = blockIdx.x * 128;

    const float rb0 = relpos[h * 5 + 0];
    const float rb1 = relpos[h * 5 + 1];
    const float rb2 = relpos[h * 5 + 2];
    const float rb3 = relpos[h * 5 + 3];
    const float rb4 = relpos[h * 5 + 4];

    // Q tile load (128 rows x 128B, SW128)
    {
        const int row = tid >> 1;
        const int ch0 = (tid & 1) * 4;
        const size_t gb = (size_t)(b * SEQ + q0 + row) * DMODEL + h * HDIM + ch0 * 8;
#pragma unroll
        for (int ci = 0; ci < 4; ci++) {
            const uint32_t off = SW128((uint32_t)(row * 128 + (ch0 + ci) * 16));
            *(uint4*)(smp + OQH + off) = *(const uint4*)(Qh + gb + ci * 8);
        }
    }

    // K/V loader: 64 rows x 128B; thread -> row=tid>>2, 2x16B chunks
    const int krow = tid >> 2;
    const int kch = tid & 3;
    const size_t kgb0 = (size_t)(b * SEQ + krow) * DMODEL + h * HDIM + kch * 16;
    const uint32_t loff0 = SW128((uint32_t)(krow * 128 + kch * 32));
    const uint32_t loff1 = SW128((uint32_t)(krow * 128 + kch * 32 + 16));

    // prologue: stages 0..NSTAGE-2
#pragma unroll
    for (int s = 0; s < NSTAGE - 1; s++) {
        const uint32_t st = sb + OST + s * STAGE_SZ;
        const size_t gb = kgb0 + (size_t)(s * 64) * DMODEL;
        cpa16(st + SKH + loff0, Kh + gb);  cpa16(st + SKH + loff1, Kh + gb + 8);
        cpa16(st + SVH + loff0, Vh + gb);  cpa16(st + SVH + loff1, Vh + gb + 8);
        CP_COMMIT();
    }

    const uint32_t base_qa = (uint32_t)((16 * w + (lane & 15)) * 128 + 16 * (lane >> 4));
    const uint32_t base_kb = (uint32_t)(((lane & 7) + ((lane & 16) >> 1)) * 128 + ((lane >> 3) & 1) * 16);
    const uint32_t base_vb = (uint32_t)(((lane & 7) + (lane & 8)) * 128 + ((lane >> 4) & 1) * 16);

    float co[8][4];
#pragma unroll
    for (int i = 0; i < 8; i++)
#pragma unroll
        for (int j = 0; j < 4; j++) co[i][j] = 0.f;
    float sum0 = 0.f, sum1 = 0.f;

    const int r0g = q0 + 16 * w + (lane >> 2);
    const int kcol_off = 2 * (lane & 3);

    for (int kt = 0; kt < NKT; kt++) {
        const int k0 = kt * 64;

        CP_WAIT2();           // stage kt's group complete
        __syncthreads();      // all threads done with the stage being overwritten

        // issue stage kt+NSTAGE-1 (its buffer is now free)
        if (kt + NSTAGE - 1 < NKT) {
            const uint32_t st = sb + OST + ((kt + NSTAGE - 1) % NSTAGE) * STAGE_SZ;
            const size_t gb = kgb0 + (size_t)((kt + NSTAGE - 1) * 64) * DMODEL;
            cpa16(st + SKH + loff0, Kh + gb);  cpa16(st + SKH + loff1, Kh + gb + 8);
            cpa16(st + SVH + loff0, Vh + gb);  cpa16(st + SVH + loff1, Vh + gb + 8);
        }
        CP_COMMIT();

        const uint32_t st = sb + OST + (kt % NSTAGE) * STAGE_SZ;
        const uint32_t KHb = st + SKH, VHb = st + SVH;
        const uint32_t QHb = sb + OQH;

        // ---- S = Q @ K^T (fp16) ----
        float cs[8][4];
#pragma unroll
        for (int i = 0; i < 8; i++)
#pragma unroll
            for (int j = 0; j < 4; j++) cs[i][j] = 0.f;

#pragma unroll
        for (int c = 0; c < 4; c++) {
            uint32_t ah[4];
            ldsm4(ah, QHb + SW128(base_qa + 32 * c));
#pragma unroll
            for (int j2 = 0; j2 < 4; j2++) {
                uint32_t bh[4];
                ldsm4(bh, KHb + SW128(base_kb + 2048u * j2 + 32u * c));
                mmaf16(cs[2 * j2], ah, bh[0], bh[1]);
                mmaf16(cs[2 * j2 + 1], ah, bh[2], bh[3]);
            }
        }

        // ---- bias + exp + rowsum ----
        const bool uni = (k0 - (q0 + 127) > MAXREL) || ((k0 + 63) - q0 < -MAXREL);
        if (uni) {
            const float ub = (k0 > q0) ? rb4 : rb0;
#pragma unroll
            for (int j = 0; j < 8; j++) {
                cs[j][0] = __expf(cs[j][0] + ub);
                cs[j][1] = __expf(cs[j][1] + ub);
                cs[j][2] = __expf(cs[j][2] + ub);
                cs[j][3] = __expf(cs[j][3] + ub);
            }
        } else {
#pragma unroll
            for (int j = 0; j < 8; j++) {
                const int kc = k0 + 8 * j + kcol_off;
#pragma unroll
                for (int i = 0; i < 4; i++) {
                    const int rel = (kc + (i & 1)) - (r0g + (i >> 1) * 8);
                    const float bb = rel <= -MAXREL ? rb0 :
                                     rel >= MAXREL ? rb4 :
                                     rel == -1 ? rb1 : (rel == 0 ? rb2 : rb3);
                    cs[j][i] = __expf(cs[j][i] + bb);
                }
            }
        }
#pragma unroll
        for (int j = 0; j < 8; j++) {
            sum0 += cs[j][0] + cs[j][1];
            sum1 += cs[j][2] + cs[j][3];
        }

        // ---- O += P @ V (fp16) ----
#pragma unroll
        for (int kc = 0; kc < 4; kc++) {
            uint32_t ph[4];
            ph[0] = pkhf2(cs[2 * kc][0],     cs[2 * kc][1]);
            ph[1] = pkhf2(cs[2 * kc][2],     cs[2 * kc][3]);
            ph[2] = pkhf2(cs[2 * kc + 1][0], cs[2 * kc + 1][1]);
            ph[3] = pkhf2(cs[2 * kc + 1][2], cs[2 * kc + 1][3]);
#pragma unroll
            for (int jv = 0; jv < 4; jv++) {
                uint32_t vh[4];
                ldsm4t(vh, VHb + SW128(base_vb + 2048u * kc + 32u * jv));
                mmaf16(co[2 * jv], ph, vh[0], vh[1]);
                mmaf16(co[2 * jv + 1], ph, vh[2], vh[3]);
            }
        }
    }

    sum0 += __shfl_xor_sync(0xFFFFFFFFu, sum0, 1);
    sum0 += __shfl_xor_sync(0xFFFFFFFFu, sum0, 2);
    sum1 += __shfl_xor_sync(0xFFFFFFFFu, sum1, 1);
    sum1 += __shfl_xor_sync(0xFFFFFFFFu, sum1, 2);
    const float inv0 = 1.0f / sum0;
    const float inv1 = 1.0f / sum1;

    {
        float* O0 = Out + (size_t)(b * SEQ + r0g) * DMODEL + h * HDIM + kcol_off;
        float* O1 = O0 + 8 * DMODEL;
#pragma unroll
        for (int j = 0; j < 8; j++) {
            *(float2*)(O0 + 8 * j) = make_float2(co[j][0] * inv0, co[j][1] * inv0);
            *(float2*)(O1 + 8 * j) = make_float2(co[j][2] * inv1, co[j][3] * inv1);
        }
    }
}

// ---------------------------------------------------------------------------
extern "C" void kernel_launch(void* const* d_in, const int* in_sizes, int n_in,
                              void* d_out, int out_size)
{
    const float* q  = (const float*)d_in[0];
    const float* k  = (const float*)d_in[1];
    const float* v  = (const float*)d_in[2];
    const float* Wq = (const float*)d_in[3];
    const float* bq = (const float*)d_in[4];
    const float* Wk = (const float*)d_in[5];
    const float* bk = (const float*)d_in[6];
    const float* Wv = (const float*)d_in[7];
    const float* bv = (const float*)d_in[8];
    const float* Wo = (const float*)d_in[9];
    const float* bo = (const float*)d_in[10];
    const float* rp = (const float*)d_in[11];
    float* out = (float*)d_out;

    float *dA;
    unsigned short *dQh, *dKh, *dVh;
    cudaGetSymbolAddress((void**)&dA, g_A);
    cudaGetSymbolAddress((void**)&dQh, g_Qh);
    cudaGetSymbolAddress((void**)&dKh, g_Kh);
    cudaGetSymbolAddress((void**)&dVh, g_Vh);

    cudaFuncSetAttribute(attn_kernel, cudaFuncAttributeMaxDynamicSharedMemorySize,
                         ATTN_SMEM);
    cudaFuncSetAttribute(gemm_bf16, cudaFuncAttributeMaxDynamicSharedMemorySize,
                         GEMM_SMEM);

    dim3 gblk(256);
    dim3 ggrid(DMODEL / 128, MROWS / 128);   // (4, 64)

    gemm_bf16<<<ggrid, gblk, GEMM_SMEM>>>(q, Wq, bq, nullptr, dQh, 0.125f, 1);
    gemm_bf16<<<ggrid, gblk, GEMM_SMEM>>>(k, Wk, bk, nullptr, dKh, 1.0f, 1);
    gemm_bf16<<<ggrid, gblk, GEMM_SMEM>>>(v, Wv, bv, nullptr, dVh, 1.0f, 1);

    dim3 agrid(SEQ / 128, NHEAD, BATCH);     // (32, 8, 2)
    attn_kernel<<<agrid, gblk, ATTN_SMEM>>>(dQh, dKh, dVh, rp, dA);

    gemm_bf16<<<ggrid, gblk, GEMM_SMEM>>>(dA, Wo, bo, out, nullptr, 1.0f, 0);
}

// round 16
// speedup vs baseline: 1.1859x; 1.0664x over previous
#include <cuda_runtime.h>
#include <cuda_bf16.h>
#include <cuda_fp16.h>
#include <math.h>
#include <stdint.h>

#define BATCH 2
#define SEQ   4096
#define DMODEL 512
#define NHEAD 8
#define HDIM  64
#define MROWS (BATCH*SEQ)
#define MAXREL 2
#define LOG2E 1.44269504f

typedef unsigned long long ull;

// scratch
__device__ unsigned short g_Qh[MROWS * DMODEL];       // fp16 (Q, pre-scaled 0.125*log2e)
__device__ unsigned short g_Kh[MROWS * DMODEL];       // fp16
__device__ unsigned short g_Vh[MROWS * DMODEL];       // fp16
__device__ unsigned short g_Ih[3 * MROWS * DMODEL];   // bf16 hi of q,k,v inputs
__device__ unsigned short g_Il[3 * MROWS * DMODEL];   // bf16 lo
__device__ unsigned short g_WhA[4 * DMODEL * DMODEL]; // bf16 hi of Wq,Wk,Wv,Wo
__device__ unsigned short g_WlA[4 * DMODEL * DMODEL]; // bf16 lo
__device__ unsigned short g_Ah[MROWS * DMODEL];       // bf16 hi of attn out
__device__ unsigned short g_Al[MROWS * DMODEL];       // bf16 lo

// split (a,b) into bf16 hi-pair + lo-pair words: h={lo=a,hi=b}
__device__ __forceinline__ void split2(float a, float b, uint32_t& h, uint32_t& l) {
    asm("cvt.rn.bf16x2.f32 %0, %1, %2;" : "=r"(h) : "f"(b), "f"(a));
    float ha = __uint_as_float(h << 16);
    float hb = __uint_as_float(h & 0xffff0000u);
    float ra = a - ha, rb = b - hb;
    asm("cvt.rn.bf16x2.f32 %0, %1, %2;" : "=r"(l) : "f"(rb), "f"(ra));
}
// pack (a,b) -> fp16x2 {lo=a, hi=b}
__device__ __forceinline__ uint32_t pkhf2(float a, float b) {
    uint32_t h;
    asm("cvt.rn.f16x2.f32 %0, %1, %2;" : "=r"(h) : "f"(b), "f"(a));
    return h;
}
__device__ __forceinline__ float ex2f(float x) {
    float y; asm("ex2.approx.f32 %0, %1;" : "=f"(y) : "f"(x)); return y;
}

static __device__ __forceinline__ uint32_t smem_u32(const void* p) {
    uint32_t a;
    asm("{ .reg .u64 t; cvta.to.shared.u64 t, %1; cvt.u32.u64 %0, t; }" : "=r"(a) : "l"(p));
    return a;
}
__device__ __forceinline__ void ldsm4(uint32_t* r, uint32_t addr) {
    asm volatile("ldmatrix.sync.aligned.m8n8.x4.shared.b16 {%0,%1,%2,%3}, [%4];"
                 : "=r"(r[0]), "=r"(r[1]), "=r"(r[2]), "=r"(r[3]) : "r"(addr));
}
__device__ __forceinline__ void ldsm4t(uint32_t* r, uint32_t addr) {
    asm volatile("ldmatrix.sync.aligned.m8n8.x4.trans.shared.b16 {%0,%1,%2,%3}, [%4];"
                 : "=r"(r[0]), "=r"(r[1]), "=r"(r[2]), "=r"(r[3]) : "r"(addr));
}
__device__ __forceinline__ void mmabf16(float* c, const uint32_t* a, uint32_t b0, uint32_t b1) {
    asm volatile("mma.sync.aligned.m16n8k16.row.col.f32.bf16.bf16.f32 "
                 "{%0,%1,%2,%3}, {%4,%5,%6,%7}, {%8,%9}, {%0,%1,%2,%3};"
                 : "+f"(c[0]), "+f"(c[1]), "+f"(c[2]), "+f"(c[3])
                 : "r"(a[0]), "r"(a[1]), "r"(a[2]), "r"(a[3]), "r"(b0), "r"(b1));
}
__device__ __forceinline__ void mmaf16(float* c, const uint32_t* a, uint32_t b0, uint32_t b1) {
    asm volatile("mma.sync.aligned.m16n8k16.row.col.f32.f16.f16.f32 "
                 "{%0,%1,%2,%3}, {%4,%5,%6,%7}, {%8,%9}, {%0,%1,%2,%3};"
                 : "+f"(c[0]), "+f"(c[1]), "+f"(c[2]), "+f"(c[3])
                 : "r"(a[0]), "r"(a[1]), "r"(a[2]), "r"(a[3]), "r"(b0), "r"(b1));
}
__device__ __forceinline__ void cpa16(uint32_t d, const void* s) {
    asm volatile("cp.async.cg.shared.global [%0], [%1], 16;" :: "r"(d), "l"(s));
}
#define CP_COMMIT() asm volatile("cp.async.commit_group;" ::: "memory")
#define CP_WAIT0()  asm volatile("cp.async.wait_group 0;" ::: "memory")
#define CP_WAIT2()  asm volatile("cp.async.wait_group 2;" ::: "memory")

#define SW128(o) ((o) ^ (((o) >> 3) & 0x70))
#define SW64(o)  ((o) ^ (((o) >> 3) & 0x30))

// ---------------------------------------------------------------------------
// Pre-split kernels
// ---------------------------------------------------------------------------
__global__ __launch_bounds__(256) void split_x3(const float* __restrict__ q,
                                                const float* __restrict__ k,
                                                const float* __restrict__ v)
{
    const float* srcs[3] = {q, k, v};
    const int sel = blockIdx.y;
    const size_t i = (size_t)blockIdx.x * 256 + threadIdx.x;   // float4 index
    float4 x = ((const float4*)srcs[sel])[i];
    uint2 h, l;
    split2(x.x, x.y, h.x, l.x);
    split2(x.z, x.w, h.y, l.y);
    ((uint2*)(g_Ih + (size_t)sel * MROWS * DMODEL))[i] = h;
    ((uint2*)(g_Il + (size_t)sel * MROWS * DMODEL))[i] = l;
}

__global__ __launch_bounds__(256) void split_w4(const float* __restrict__ W0,
                                                const float* __restrict__ W1,
                                                const float* __restrict__ W2,
                                                const float* __restrict__ W3)
{
    const float* srcs[4] = {W0, W1, W2, W3};
    const int sel = blockIdx.y;
    const size_t i = (size_t)blockIdx.x * 256 + threadIdx.x;   // float4 index
    float4 x = ((const float4*)srcs[sel])[i];
    uint2 h, l;
    split2(x.x, x.y, h.x, l.x);
    split2(x.z, x.w, h.y, l.y);
    ((uint2*)(g_WhA + (size_t)sel * DMODEL * DMODEL))[i] = h;
    ((uint2*)(g_WlA + (size_t)sel * DMODEL * DMODEL))[i] = l;
}

// ---------------------------------------------------------------------------
// Tensor-core GEMM on PRE-SPLIT bf16 hi/lo operands, pure cp.async 2-stage.
// C[M,512] = (Xh+Xl) @ (Wh+Wl)^T + bias (3-term).
// mode 0: fp32 out.  mode 1: fp16 out, value = scale*(acc+bias).
// ---------------------------------------------------------------------------
#define GEMM_SMEM 65536
#define GBUF 32768
#define GXH 0
#define GXL 8192
#define GWH 16384
#define GWL 24576

__global__ __launch_bounds__(256, 2) void gemm_pre(const unsigned short* __restrict__ Xh,
                                                   const unsigned short* __restrict__ Xl,
                                                   const unsigned short* __restrict__ Wh,
                                                   const unsigned short* __restrict__ Wl,
                                                   const float* __restrict__ bias,
                                                   float* __restrict__ Cf,
                                                   unsigned short* __restrict__ Ch,
                                                   float scale, int mode)
{
    extern __shared__ char gsm[];
    const uint32_t sb = smem_u32(gsm);

    const int tid = threadIdx.x;
    const int w = tid >> 5;
    const int lane = tid & 31;
    const int m0 = blockIdx.y * 128, n0 = blockIdx.x * 128;

    const int row = tid >> 1;            // 0..127
    const int cp2 = (tid & 1) * 2;       // chunk pair base (16B chunks of 64B row)

    const size_t xrow = (size_t)(m0 + row) * DMODEL;
    const size_t wrow = (size_t)(n0 + row) * DMODEL;

    const uint32_t base_a = (uint32_t)((16 * w + (lane & 15)) * 64 + (lane >> 4) * 16);
    const uint32_t base_b = (uint32_t)(((lane & 7) + ((lane & 16) >> 1)) * 64 + ((lane >> 3) & 1) * 16);

    float cs[16][4];
#pragma unroll
    for (int i = 0; i < 16; i++)
#pragma unroll
        for (int j = 0; j < 4; j++) cs[i][j] = 0.f;

    // prologue: stage 0
    {
        const uint32_t st = sb;
#pragma unroll
        for (int c2 = 0; c2 < 2; c2++) {
            const int ch = cp2 + c2;
            const uint32_t soff = SW64((uint32_t)(row * 64 + ch * 16));
            const size_t ge = (size_t)(ch * 8);
            cpa16(st + GXH + soff, Xh + xrow + ge);
            cpa16(st + GXL + soff, Xl + xrow + ge);
            cpa16(st + GWH + soff, Wh + wrow + ge);
            cpa16(st + GWL + soff, Wl + wrow + ge);
        }
    }
    CP_COMMIT();

    for (int ks = 0; ks < DMODEL / 32; ks++) {
        CP_WAIT0();        // stage ks arrived
        __syncthreads();   // all warps done with the other buffer (iter ks-1)

        if (ks + 1 < DMODEL / 32) {
            const uint32_t st = sb + (uint32_t)((ks + 1) & 1) * GBUF;
            const size_t gk = (size_t)((ks + 1) * 32);
#pragma unroll
            for (int c2 = 0; c2 < 2; c2++) {
                const int ch = cp2 + c2;
                const uint32_t soff = SW64((uint32_t)(row * 64 + ch * 16));
                const size_t ge = gk + (size_t)(ch * 8);
                cpa16(st + GXH + soff, Xh + xrow + ge);
                cpa16(st + GXL + soff, Xl + xrow + ge);
                cpa16(st + GWH + soff, Wh + wrow + ge);
                cpa16(st + GWL + soff, Wl + wrow + ge);
            }
        }
        CP_COMMIT();

        const uint32_t bp = sb + (uint32_t)(ks & 1) * GBUF;
#pragma unroll
        for (int c = 0; c < 2; c++) {
            uint32_t ah[4], al[4];
            const uint32_t aoff = SW64(base_a + 32u * c);
            ldsm4(ah, bp + GXH + aoff);
            ldsm4(al, bp + GXL + aoff);
#pragma unroll
            for (int j2 = 0; j2 < 8; j2++) {
                uint32_t bh[4], bl[4];
                const uint32_t boff = SW64(base_b + 1024u * j2 + 32u * c);
                ldsm4(bh, bp + GWH + boff);
                ldsm4(bl, bp + GWL + boff);
                mmabf16(cs[2 * j2], ah, bh[0], bh[1]);
                mmabf16(cs[2 * j2], ah, bl[0], bl[1]);
                mmabf16(cs[2 * j2], al, bh[0], bh[1]);
                mmabf16(cs[2 * j2 + 1], ah, bh[2], bh[3]);
                mmabf16(cs[2 * j2 + 1], ah, bl[2], bl[3]);
                mmabf16(cs[2 * j2 + 1], al, bh[2], bh[3]);
            }
        }
    }

    const int rr = m0 + 16 * w + (lane >> 2);
    const int cc = 2 * (lane & 3);
    if (mode == 0) {
#pragma unroll
        for (int t = 0; t < 16; t++) {
            const int col = n0 + 8 * t + cc;
            const float2 bv = *(const float2*)(bias + col);
            float* C0 = Cf + (size_t)rr * DMODEL + col;
            *(float2*)C0 = make_float2(cs[t][0] + bv.x, cs[t][1] + bv.y);
            *(float2*)(C0 + 8 * DMODEL) = make_float2(cs[t][2] + bv.x, cs[t][3] + bv.y);
        }
    } else {
#pragma unroll
        for (int t = 0; t < 16; t++) {
            const int col = n0 + 8 * t + cc;
            const float2 bv = *(const float2*)(bias + col);
            *(uint32_t*)(Ch + (size_t)rr * DMODEL + col) =
                pkhf2(scale * (cs[t][0] + bv.x), scale * (cs[t][1] + bv.y));
            *(uint32_t*)(Ch + (size_t)(rr + 8) * DMODEL + col) =
                pkhf2(scale * (cs[t][2] + bv.x), scale * (cs[t][3] + bv.y));
        }
    }
}

// ===========================================================================
// mma.sync attention — R11/R14 structure; exp2-domain scores; epilogue emits
// bf16 hi/lo of the attention output (for the O-projection GEMM).
// ===========================================================================

#define OQH 0
#define OST 16384
#define STAGE_SZ 16384
#define SKH 0
#define SVH 8192
#define NSTAGE 4
#define ATTN_SMEM (OST + NSTAGE * STAGE_SZ)   /* 80 KB */
#define NKT (SEQ / 64)

__global__ __launch_bounds__(256, 2) void attn_kernel(
    const unsigned short* __restrict__ Qh,
    const unsigned short* __restrict__ Kh,
    const unsigned short* __restrict__ Vh,
    const float* __restrict__ relpos,
    unsigned short* __restrict__ Ah,
    unsigned short* __restrict__ Al)
{
    extern __shared__ char smp[];
    const uint32_t sb = smem_u32(smp);

    const int tid = threadIdx.x;
    const int w = tid >> 5;
    const int lane = tid & 31;
    const int b = blockIdx.z, h = blockIdx.y;
    const int q0 = blockIdx.x * 128;

    // biases pre-scaled to exp2 domain
    const float rb0 = relpos[h * 5 + 0] * LOG2E;
    const float rb1 = relpos[h * 5 + 1] * LOG2E;
    const float rb2 = relpos[h * 5 + 2] * LOG2E;
    const float rb3 = relpos[h * 5 + 3] * LOG2E;
    const float rb4 = relpos[h * 5 + 4] * LOG2E;

    // Q tile load (128 rows x 128B, SW128)
    {
        const int row = tid >> 1;
        const int ch0 = (tid & 1) * 4;
        const size_t gb = (size_t)(b * SEQ + q0 + row) * DMODEL + h * HDIM + ch0 * 8;
#pragma unroll
        for (int ci = 0; ci < 4; ci++) {
            const uint32_t off = SW128((uint32_t)(row * 128 + (ch0 + ci) * 16));
            *(uint4*)(smp + OQH + off) = *(const uint4*)(Qh + gb + ci * 8);
        }
    }

    // K/V loader: 64 rows x 128B; thread -> row=tid>>2, 2x16B chunks
    const int krow = tid >> 2;
    const int kch = tid & 3;
    const size_t kgb0 = (size_t)(b * SEQ + krow) * DMODEL + h * HDIM + kch * 16;
    const uint32_t loff0 = SW128((uint32_t)(krow * 128 + kch * 32));
    const uint32_t loff1 = SW128((uint32_t)(krow * 128 + kch * 32 + 16));

    // prologue: stages 0..NSTAGE-2
#pragma unroll
    for (int s = 0; s < NSTAGE - 1; s++) {
        const uint32_t st = sb + OST + s * STAGE_SZ;
        const size_t gb = kgb0 + (size_t)(s * 64) * DMODEL;
        cpa16(st + SKH + loff0, Kh + gb);  cpa16(st + SKH + loff1, Kh + gb + 8);
        cpa16(st + SVH + loff0, Vh + gb);  cpa16(st + SVH + loff1, Vh + gb + 8);
        CP_COMMIT();
    }

    const uint32_t base_qa = (uint32_t)((16 * w + (lane & 15)) * 128 + 16 * (lane >> 4));
    const uint32_t base_kb = (uint32_t)(((lane & 7) + ((lane & 16) >> 1)) * 128 + ((lane >> 3) & 1) * 16);
    const uint32_t base_vb = (uint32_t)(((lane & 7) + (lane & 8)) * 128 + ((lane >> 4) & 1) * 16);

    float co[8][4];
#pragma unroll
    for (int i = 0; i < 8; i++)
#pragma unroll
        for (int j = 0; j < 4; j++) co[i][j] = 0.f;
    float sum0 = 0.f, sum1 = 0.f;

    const int r0g = q0 + 16 * w + (lane >> 2);
    const int kcol_off = 2 * (lane & 3);

    for (int kt = 0; kt < NKT; kt++) {
        const int k0 = kt * 64;

        CP_WAIT2();
        __syncthreads();

        if (kt + NSTAGE - 1 < NKT) {
            const uint32_t st = sb + OST + ((kt + NSTAGE - 1) % NSTAGE) * STAGE_SZ;
            const size_t gb = kgb0 + (size_t)((kt + NSTAGE - 1) * 64) * DMODEL;
            cpa16(st + SKH + loff0, Kh + gb);  cpa16(st + SKH + loff1, Kh + gb + 8);
            cpa16(st + SVH + loff0, Vh + gb);  cpa16(st + SVH + loff1, Vh + gb + 8);
        }
        CP_COMMIT();

        const uint32_t st = sb + OST + (kt % NSTAGE) * STAGE_SZ;
        const uint32_t KHb = st + SKH, VHb = st + SVH;
        const uint32_t QHb = sb + OQH;

        // ---- S = Q @ K^T (fp16; scores already in log2 domain) ----
        float cs[8][4];
#pragma unroll
        for (int i = 0; i < 8; i++)
#pragma unroll
            for (int j = 0; j < 4; j++) cs[i][j] = 0.f;

#pragma unroll
        for (int c = 0; c < 4; c++) {
            uint32_t ah[4];
            ldsm4(ah, QHb + SW128(base_qa + 32 * c));
#pragma unroll
            for (int j2 = 0; j2 < 4; j2++) {
                uint32_t bh[4];
                ldsm4(bh, KHb + SW128(base_kb + 2048u * j2 + 32u * c));
                mmaf16(cs[2 * j2], ah, bh[0], bh[1]);
                mmaf16(cs[2 * j2 + 1], ah, bh[2], bh[3]);
            }
        }

        // ---- bias + exp2 + rowsum ----
        const bool uni = (k0 - (q0 + 127) > MAXREL) || ((k0 + 63) - q0 < -MAXREL);
        if (uni) {
            const float ub = (k0 > q0) ? rb4 : rb0;
#pragma unroll
            for (int j = 0; j < 8; j++) {
                cs[j][0] = ex2f(cs[j][0] + ub);
                cs[j][1] = ex2f(cs[j][1] + ub);
                cs[j][2] = ex2f(cs[j][2] + ub);
                cs[j][3] = ex2f(cs[j][3] + ub);
            }
        } else {
#pragma unroll
            for (int j = 0; j < 8; j++) {
                const int kc = k0 + 8 * j + kcol_off;
#pragma unroll
                for (int i = 0; i < 4; i++) {
                    const int rel = (kc + (i & 1)) - (r0g + (i >> 1) * 8);
                    const float bb = rel <= -MAXREL ? rb0 :
                                     rel >= MAXREL ? rb4 :
                                     rel == -1 ? rb1 : (rel == 0 ? rb2 : rb3);
                    cs[j][i] = ex2f(cs[j][i] + bb);
                }
            }
        }
#pragma unroll
        for (int j = 0; j < 8; j++) {
            sum0 += cs[j][0] + cs[j][1];
            sum1 += cs[j][2] + cs[j][3];
        }

        // ---- O += P @ V (fp16) ----
#pragma unroll
        for (int kc = 0; kc < 4; kc++) {
            uint32_t ph[4];
            ph[0] = pkhf2(cs[2 * kc][0],     cs[2 * kc][1]);
            ph[1] = pkhf2(cs[2 * kc][2],     cs[2 * kc][3]);
            ph[2] = pkhf2(cs[2 * kc + 1][0], cs[2 * kc + 1][1]);
            ph[3] = pkhf2(cs[2 * kc + 1][2], cs[2 * kc + 1][3]);
#pragma unroll
            for (int jv = 0; jv < 4; jv++) {
                uint32_t vh[4];
                ldsm4t(vh, VHb + SW128(base_vb + 2048u * kc + 32u * jv));
                mmaf16(co[2 * jv], ph, vh[0], vh[1]);
                mmaf16(co[2 * jv + 1], ph, vh[2], vh[3]);
            }
        }
    }

    sum0 += __shfl_xor_sync(0xFFFFFFFFu, sum0, 1);
    sum0 += __shfl_xor_sync(0xFFFFFFFFu, sum0, 2);
    sum1 += __shfl_xor_sync(0xFFFFFFFFu, sum1, 1);
    sum1 += __shfl_xor_sync(0xFFFFFFFFu, sum1, 2);
    const float inv0 = 1.0f / sum0;
    const float inv1 = 1.0f / sum1;

    // epilogue: emit bf16 hi/lo of attention output (for O-proj GEMM)
    {
        const size_t base0 = (size_t)(b * SEQ + r0g) * DMODEL + h * HDIM + kcol_off;
        const size_t base1 = base0 + (size_t)8 * DMODEL;
#pragma unroll
        for (int j = 0; j < 8; j++) {
            uint32_t hh, ll;
            split2(co[j][0] * inv0, co[j][1] * inv0, hh, ll);
            *(uint32_t*)(Ah + base0 + 8 * j) = hh;
            *(uint32_t*)(Al + base0 + 8 * j) = ll;
            split2(co[j][2] * inv1, co[j][3] * inv1, hh, ll);
            *(uint32_t*)(Ah + base1 + 8 * j) = hh;
            *(uint32_t*)(Al + base1 + 8 * j) = ll;
        }
    }
}

// ---------------------------------------------------------------------------
extern "C" void kernel_launch(void* const* d_in, const int* in_sizes, int n_in,
                              void* d_out, int out_size)
{
    const float* q  = (const float*)d_in[0];
    const float* k  = (const float*)d_in[1];
    const float* v  = (const float*)d_in[2];
    const float* Wq = (const float*)d_in[3];
    const float* bq = (const float*)d_in[4];
    const float* Wk = (const float*)d_in[5];
    const float* bk = (const float*)d_in[6];
    const float* Wv = (const float*)d_in[7];
    const float* bv = (const float*)d_in[8];
    const float* Wo = (const float*)d_in[9];
    const float* bo = (const float*)d_in[10];
    const float* rp = (const float*)d_in[11];
    float* out = (float*)d_out;

    unsigned short *dQh, *dKh, *dVh, *dIh, *dIl, *dWh, *dWl, *dAh, *dAl;
    cudaGetSymbolAddress((void**)&dQh, g_Qh);
    cudaGetSymbolAddress((void**)&dKh, g_Kh);
    cudaGetSymbolAddress((void**)&dVh, g_Vh);
    cudaGetSymbolAddress((void**)&dIh, g_Ih);
    cudaGetSymbolAddress((void**)&dIl, g_Il);
    cudaGetSymbolAddress((void**)&dWh, g_WhA);
    cudaGetSymbolAddress((void**)&dWl, g_WlA);
    cudaGetSymbolAddress((void**)&dAh, g_Ah);
    cudaGetSymbolAddress((void**)&dAl, g_Al);

    cudaFuncSetAttribute(attn_kernel, cudaFuncAttributeMaxDynamicSharedMemorySize,
                         ATTN_SMEM);
    cudaFuncSetAttribute(gemm_pre, cudaFuncAttributeMaxDynamicSharedMemorySize,
                         GEMM_SMEM);

    dim3 gblk(256);

    // pre-split inputs and weights
    split_x3<<<dim3(MROWS * DMODEL / 4 / 256, 3), gblk>>>(q, k, v);
    split_w4<<<dim3(DMODEL * DMODEL / 4 / 256, 4), gblk>>>(Wq, Wk, Wv, Wo);

    const size_t NI = (size_t)MROWS * DMODEL;
    const size_t NW = (size_t)DMODEL * DMODEL;
    dim3 ggrid(DMODEL / 128, MROWS / 128);   // (4, 64)

    gemm_pre<<<ggrid, gblk, GEMM_SMEM>>>(dIh + 0 * NI, dIl + 0 * NI, dWh + 0 * NW, dWl + 0 * NW,
                                         bq, nullptr, dQh, 0.125f * LOG2E, 1);
    gemm_pre<<<ggrid, gblk, GEMM_SMEM>>>(dIh + 1 * NI, dIl + 1 * NI, dWh + 1 * NW, dWl + 1 * NW,
                                         bk, nullptr, dKh, 1.0f, 1);
    gemm_pre<<<ggrid, gblk, GEMM_SMEM>>>(dIh + 2 * NI, dIl + 2 * NI, dWh + 2 * NW, dWl + 2 * NW,
                                         bv, nullptr, dVh, 1.0f, 1);

    dim3 agrid(SEQ / 128, NHEAD, BATCH);     // (32, 8, 2)
    attn_kernel<<<agrid, gblk, ATTN_SMEM>>>(dQh, dKh, dVh, rp, dAh, dAl);

    gemm_pre<<<ggrid, gblk, GEMM_SMEM>>>(dAh, dAl, dWh + 3 * NW, dWl + 3 * NW,
                                         bo, out, nullptr, 1.0f, 0);
}